// round 17
// baseline (speedup 1.0000x reference)
#include <cuda_runtime.h>
#include <cuda_fp16.h>
#include <cstdint>

// Problem dims
#define BB    128
#define TT    512
#define DIN   256
#define DH    512
#define G4    2048        // 4*DH
#define DOUT  256
#define RCTA  128         // 8 batch groups x 16 col groups

// ---------------- static device scratch ----------------
__device__ __half g_wx [(size_t)G4 * DIN];            // w_x2h permuted, [p][k]
__device__ __half g_wh [(size_t)G4 * DH];             // w_h2h permuted, [p][k]
__device__ float  g_gbias[G4];                        // permuted biases
// h double buffer, CHUNK-MAJOR: [buf][bg][cg][16 rows][32 units]
__device__ __half g_hbuf[2][BB * DH];
__device__ float  g_hlast[BB * DH];                   // final h fp32
__device__ int    g_flags[RCTA];                      // per-CTA publish flags

// permuted gate column: p = cg*128 + w*16 + q*4 + u
__device__ __forceinline__ int gate_col(int p) {
    return ((p >> 2) & 3) * DH + (p >> 7) * 32 + (((p >> 4) & 7) << 2) + (p & 3);
}

__device__ __forceinline__ void mma16816(float& d0, float& d1, float& d2, float& d3,
                                         unsigned a0, unsigned a1, unsigned a2, unsigned a3,
                                         unsigned b0, unsigned b1) {
    asm volatile(
        "mma.sync.aligned.m16n8k16.row.col.f32.f16.f16.f32 "
        "{%0,%1,%2,%3}, {%4,%5,%6,%7}, {%8,%9}, {%0,%1,%2,%3};"
        : "+f"(d0), "+f"(d1), "+f"(d2), "+f"(d3)
        : "r"(a0), "r"(a1), "r"(a2), "r"(a3), "r"(b0), "r"(b1));
}

__device__ __forceinline__ void ldsm_x4(unsigned& a0, unsigned& a1, unsigned& a2, unsigned& a3,
                                        uint32_t addr) {
    asm volatile("ldmatrix.sync.aligned.m8n8.x4.shared.b16 {%0,%1,%2,%3}, [%4];"
                 : "=r"(a0), "=r"(a1), "=r"(a2), "=r"(a3) : "r"(addr));
}

__device__ __forceinline__ uint32_t smem_u32(const void* p) {
    uint32_t a;
    asm("{ .reg .u64 t; cvta.to.shared.u64 t, %1; cvt.u32.u64 %0, t; }" : "=r"(a) : "l"(p));
    return a;
}

__device__ __forceinline__ void stg_cg_u16(__half* p, __half v) {
    unsigned short s = __half_as_ushort(v);
    asm volatile("st.global.cg.u16 [%0], %1;" :: "l"(p), "h"(s) : "memory");
}

__device__ __forceinline__ uint4 pack8h(float4 a, float4 b) {
    uint4 u;
    __half2 h0 = __floats2half2_rn(a.x, a.y);
    __half2 h1 = __floats2half2_rn(a.z, a.w);
    __half2 h2 = __floats2half2_rn(b.x, b.y);
    __half2 h3 = __floats2half2_rn(b.z, b.w);
    u.x = *(unsigned*)&h0; u.y = *(unsigned*)&h1;
    u.z = *(unsigned*)&h2; u.w = *(unsigned*)&h3;
    return u;
}

__device__ __forceinline__ float sigm(float x) { return 1.0f / (1.0f + __expf(-x)); }
__device__ __forceinline__ float tanh_a(float x) {
    x = fminf(fmaxf(x, -15.f), 15.f);
    float e = __expf(2.f * x);
    return (e - 1.f) / (e + 1.f);
}
__device__ __forceinline__ float lstm_cell(float zi, float zf, float zg, float zo, float& c) {
    float i = sigm(zi), f = sigm(zf), gg = tanh_a(zg), o = sigm(zo);
    c = fmaf(c, f, i * gg);
    return o * tanh_a(c);
}

// ---------------- prep: weights/biases/flags ----------------
__global__ void prep_w_kernel(const float* __restrict__ w_x2h, const float* __restrict__ b_x2h,
                              const float* __restrict__ w_h2h, const float* __restrict__ b_h2h) {
    int idx = blockIdx.x * 256 + threadIdx.x;   // 1,048,576 = 2048*512
    {
        int p = idx >> 9, k = idx & 511;
        g_wh[idx] = __float2half_rn(w_h2h[(size_t)k * G4 + gate_col(p)]);
    }
    if (idx < G4 * DIN) {
        int p = idx >> 8, k = idx & 255;
        g_wx[idx] = __float2half_rn(w_x2h[(size_t)k * G4 + gate_col(p)]);
    }
    if (idx < G4) {
        int gc = gate_col(idx);
        g_gbias[idx] = b_x2h[gc] + b_h2h[gc];
    }
    if (idx < RCTA) g_flags[idx] = 0;
}

// ---------------- fused persistent recurrent kernel ----------------
// R16 base. NEW: (a) fp32 x loaded+converted in-kernel (prep_x deleted);
// (b) reordered step: x-MMA absorbs producer skew BEFORE poll (unchanged),
// then after poll the h ldcg results are hidden behind x_{t+1} staging.
#define CH_STRIDE 40
#define CH_SZ     (16 * CH_STRIDE)         // 640 halves per chunk
#define WX_HALVES (128 * 264)
#define XS_HALVES (16 * 264)
#define WX_OFF    0
#define XS_OFF    WX_HALVES                // x_sm: [2][16][264]
#define HS_OFF    (WX_HALVES + 2 * XS_HALVES)
#define REC_SMEM  ((WX_HALVES + 2 * XS_HALVES + 16 * CH_SZ) * 2)   // 104,960 B

__global__ __launch_bounds__(256, 1) void rec_kernel(const float* __restrict__ x) {
    extern __shared__ __half sm[];
    __half* wx_sm = sm + WX_OFF;           // 128 x 264
    __half* x_sm  = sm + XS_OFF;           // 2 x 16 x 264
    __half* h_sm  = sm + HS_OFF;           // 16 chunks x 16 x 40

    const int tid = threadIdx.x;
    const int j = blockIdx.x;
    const int bg = j >> 4, cg = j & 15;
    const int w = tid >> 5, lane = tid & 31;
    const int g = lane >> 2, tq = lane & 3;
    const int b = tq >> 1;

    // x tile addressing: thread covers (r0,s0) and (r1,s1); 8 halves each
    const int r0x = tid >> 5, s0x = tid & 31;
    const int r1x = (tid + 256) >> 5, s1x = tid & 31;   // (tid+256)&31 == tid&31

    // -------- prologue --------
    unsigned breg[128];
    #pragma unroll
    for (int nt = 0; nt < 2; nt++) {
        const __half* wrow = g_wh + (size_t)(cg * 128 + w * 16 + nt * 8 + g) * DH + 2 * tq;
        #pragma unroll
        for (int kt = 0; kt < 32; kt++) {
            breg[nt * 64 + kt * 2]     = *(const unsigned*)(wrow + kt * 16);
            breg[nt * 64 + kt * 2 + 1] = *(const unsigned*)(wrow + kt * 16 + 8);
        }
    }
    {   // Wx slice: 128 rows x 32 uint4
        const uint4* ws = (const uint4*)(g_wx + (size_t)cg * 128 * DIN);
        #pragma unroll
        for (int ii = 0; ii < 16; ii++) {
            int i = tid + ii * 256;
            *(uint4*)&wx_sm[(i >> 5) * 264 + ((i & 31) << 3)] = ws[i];
        }
    }
    {   // x_0 tile from fp32
        const float* p0 = x + (size_t)(bg * 16 + r0x) * TT * DIN + (size_t)s0x * 8;
        const float* p1 = x + (size_t)(bg * 16 + r1x) * TT * DIN + (size_t)s1x * 8;
        float4 a0 = *(const float4*)p0, b0 = *(const float4*)(p0 + 4);
        float4 a1 = *(const float4*)p1, b1 = *(const float4*)(p1 + 4);
        *(uint4*)&x_sm[r0x * 264 + s0x * 8] = pack8h(a0, b0);
        *(uint4*)&x_sm[r1x * 264 + s1x * 8] = pack8h(a1, b1);
    }
    float2 gb0 = *(const float2*)&g_gbias[cg * 128 + w * 16 + 2 * tq];
    float2 gb1 = *(const float2*)&g_gbias[cg * 128 + w * 16 + 8 + 2 * tq];
    __syncthreads();

    const uint32_t hbase  = smem_u32(h_sm);
    const uint32_t xbase  = smem_u32(x_sm);
    const int grp = lane >> 3;
    const uint32_t laneoff_h = (uint32_t)(((grp & 1) * 8 + (lane & 7)) * CH_STRIDE
                                          + (grp >> 1) * 8);
    const uint32_t laneoff_x = (uint32_t)(((grp & 1) * 8 + (lane & 7)) * 264
                                          + (grp >> 1) * 8);

    float c0 = 0.f, c1 = 0.f;

    for (int t = 0; t < TT; t++) {
        // prefetch x_{t+1} fp32 (4 float4/thread) — in flight through x-MMA+poll
        float4 xfa0, xfb0, xfa1, xfb1;
        if (t < TT - 1) {
            const float* p0 = x + ((size_t)(bg * 16 + r0x) * TT + (t + 1)) * DIN + s0x * 8;
            const float* p1 = x + ((size_t)(bg * 16 + r1x) * TT + (t + 1)) * DIN + s1x * 8;
            xfa0 = __ldg((const float4*)p0); xfb0 = __ldg((const float4*)(p0 + 4));
            xfa1 = __ldg((const float4*)p1); xfb1 = __ldg((const float4*)(p1 + 4));
        }

        float accA[2][4], accB[2][4];
        #pragma unroll
        for (int nt = 0; nt < 2; nt++)
            #pragma unroll
            for (int e = 0; e < 4; e++) { accA[nt][e] = 0.f; accB[nt][e] = 0.f; }

        // -------- x-part MMA (absorbs producer skew before the poll) --------
        {
            const uint32_t xb = xbase + (uint32_t)((t & 1) * XS_HALVES) * 2 + laneoff_x * 2;
            #pragma unroll
            for (int kt = 0; kt < 16; kt++) {
                unsigned a0, a1, a2, a3;
                ldsm_x4(a0, a1, a2, a3, xb + kt * 32);
                const int kx = kt * 16 + 2 * tq;
                #pragma unroll
                for (int nt = 0; nt < 2; nt++) {
                    unsigned b0 = *(const unsigned*)&wx_sm[(w * 16 + nt * 8 + g) * 264 + kx];
                    unsigned b1 = *(const unsigned*)&wx_sm[(w * 16 + nt * 8 + g) * 264 + kx + 8];
                    if (kt & 1)
                        mma16816(accB[nt][0], accB[nt][1], accB[nt][2], accB[nt][3],
                                 a0, a1, a2, a3, b0, b1);
                    else
                        mma16816(accA[nt][0], accA[nt][1], accA[nt][2], accA[nt][3],
                                 a0, a1, a2, a3, b0, b1);
                }
            }
        }

        if (t > 0) {
            // R15 protocol: per-warp poll producers 2w, 2w+1
            if (lane < 2) {
                volatile int* fl = g_flags + bg * 16 + 2 * w + lane;
                while (*fl < t) { }
            }
            __syncwarp();
            asm volatile("membar.gl;" ::: "memory");

            // issue h loads into regs (latency hidden behind x staging below)
            uint4 hv[4];
            const uint4* hsrc = (const uint4*)(g_hbuf[t & 1]);
            #pragma unroll
            for (int ci = 0; ci < 2; ci++) {
                const uint4* cb = hsrc + (size_t)(bg * 16 + 2 * w + ci) * 64;
                #pragma unroll
                for (int jj = 0; jj < 2; jj++)
                    hv[ci * 2 + jj] = __ldcg(cb + lane + jj * 32);
            }

            // stage x_{t+1} (convert fp32->fp16) while h loads are in flight
            if (t < TT - 1) {
                __half* xd = x_sm + ((t + 1) & 1) * XS_HALVES;
                *(uint4*)&xd[r0x * 264 + s0x * 8] = pack8h(xfa0, xfb0);
                *(uint4*)&xd[r1x * 264 + s1x * 8] = pack8h(xfa1, xfb1);
            }

            // store h chunks to smem
            #pragma unroll
            for (int ci = 0; ci < 2; ci++) {
                const int c = 2 * w + ci;
                #pragma unroll
                for (int jj = 0; jj < 2; jj++) {
                    int n = lane + jj * 32;
                    *(uint4*)&h_sm[c * CH_SZ + (n >> 2) * CH_STRIDE + (n & 3) * 8]
                        = hv[ci * 2 + jj];
                }
            }
            __syncthreads();

            // h-part MMA: 32 kt, conflict-free ldmatrix, B in regs, chain split
            #pragma unroll
            for (int kt = 0; kt < 32; kt++) {
                const uint32_t a_addr = hbase
                    + (uint32_t)(((kt >> 1) * CH_SZ + (kt & 1) * 16) * 2) + laneoff_h * 2;
                unsigned a0, a1, a2, a3;
                ldsm_x4(a0, a1, a2, a3, a_addr);
                if (kt & 1) {
                    mma16816(accB[0][0], accB[0][1], accB[0][2], accB[0][3],
                             a0, a1, a2, a3, breg[kt * 2], breg[kt * 2 + 1]);
                    mma16816(accB[1][0], accB[1][1], accB[1][2], accB[1][3],
                             a0, a1, a2, a3, breg[64 + kt * 2], breg[64 + kt * 2 + 1]);
                } else {
                    mma16816(accA[0][0], accA[0][1], accA[0][2], accA[0][3],
                             a0, a1, a2, a3, breg[kt * 2], breg[kt * 2 + 1]);
                    mma16816(accA[1][0], accA[1][1], accA[1][2], accA[1][3],
                             a0, a1, a2, a3, breg[64 + kt * 2], breg[64 + kt * 2 + 1]);
                }
            }
        } else {
            // t == 0: no h; just stage x_1
            __half* xd = x_sm + XS_HALVES;
            *(uint4*)&xd[r0x * 264 + s0x * 8] = pack8h(xfa0, xfb0);
            *(uint4*)&xd[r1x * 264 + s1x * 8] = pack8h(xfa1, xfb1);
        }

        // combine chains + biases
        float acc[2][4];
        #pragma unroll
        for (int nt = 0; nt < 2; nt++)
            #pragma unroll
            for (int e = 0; e < 4; e++) acc[nt][e] = accA[nt][e] + accB[nt][e];
        acc[0][0] += gb0.x; acc[0][1] += gb0.y; acc[0][2] += gb0.x; acc[0][3] += gb0.y;
        acc[1][0] += gb1.x; acc[1][1] += gb1.y; acc[1][2] += gb1.x; acc[1][3] += gb1.y;

        // gate exchange (pair tq, tq^2)
        float r00 = __shfl_xor_sync(0xffffffffu, acc[0][1 - b], 2);
        float r01 = __shfl_xor_sync(0xffffffffu, acc[0][3 - b], 2);
        float r10 = __shfl_xor_sync(0xffffffffu, acc[1][1 - b], 2);
        float r11 = __shfl_xor_sync(0xffffffffu, acc[1][3 - b], 2);
        float o00 = acc[0][b],     o01 = acc[0][2 + b];
        float o10 = acc[1][b],     o11 = acc[1][2 + b];

        float zi0 = b ? r00 : o00,  zf0 = b ? o00 : r00;
        float zg0 = b ? r10 : o10,  zo0 = b ? o10 : r10;
        float zi1 = b ? r01 : o01,  zf1 = b ? o01 : r01;
        float zg1 = b ? r11 : o11,  zo1 = b ? o11 : r11;

        float h0 = lstm_cell(zi0, zf0, zg0, zo0, c0);
        float h1 = lstm_cell(zi1, zf1, zg1, zo1, c1);

        const int ul = w * 4 + (((tq & 1) << 1) | b);

        if (t < TT - 1) {
            // publish h (chunk-major), R15 protocol
            __half* hd = g_hbuf[(t + 1) & 1] + ((size_t)(bg * 16 + cg) * 16) * 32;
            stg_cg_u16(hd + g * 32 + ul,       __float2half_rn(h0));
            stg_cg_u16(hd + (g + 8) * 32 + ul, __float2half_rn(h1));
            __threadfence();
            __syncthreads();
            if (tid == 0) atomicExch(&g_flags[j], t + 1);
        } else {
            const int U = cg * 32 + ul;
            const int row0 = bg * 16 + g, row1 = row0 + 8;
            g_hlast[(size_t)row0 * DH + U] = h0;
            g_hlast[(size_t)row1 * DH + U] = h1;
        }
    }
}

// ---------------- final FC: 4 independent accumulator chains ----------------
__global__ void fc_kernel(const float* __restrict__ w_fc, const float* __restrict__ b_fc,
                          float* __restrict__ out) {
    __shared__ float hs[DH];
    int bb = blockIdx.x, o = threadIdx.x;
    for (int i = o; i < DH; i += 256) hs[i] = g_hlast[bb * DH + i];
    __syncthreads();
    float a0 = 0.f, a1 = 0.f, a2 = 0.f, a3 = 0.f;
    #pragma unroll 8
    for (int k = 0; k < DH; k += 4) {
        a0 = fmaf(hs[k],     w_fc[(size_t)k * DOUT + o],       a0);
        a1 = fmaf(hs[k + 1], w_fc[(size_t)(k + 1) * DOUT + o], a1);
        a2 = fmaf(hs[k + 2], w_fc[(size_t)(k + 2) * DOUT + o], a2);
        a3 = fmaf(hs[k + 3], w_fc[(size_t)(k + 3) * DOUT + o], a3);
    }
    out[bb * DOUT + o] = (a0 + a1) + (a2 + a3) + b_fc[o];
}

// ---------------- launch ----------------
extern "C" void kernel_launch(void* const* d_in, const int* in_sizes, int n_in,
                              void* d_out, int out_size) {
    (void)in_sizes; (void)n_in; (void)out_size;
    const float* x     = (const float*)d_in[0];
    const float* w_x2h = (const float*)d_in[1];
    const float* b_x2h = (const float*)d_in[2];
    const float* w_h2h = (const float*)d_in[3];
    const float* b_h2h = (const float*)d_in[4];
    const float* w_fc  = (const float*)d_in[5];
    const float* b_fc  = (const float*)d_in[6];
    float* out = (float*)d_out;

    cudaFuncSetAttribute(rec_kernel, cudaFuncAttributeMaxDynamicSharedMemorySize, REC_SMEM);

    prep_w_kernel<<<4096, 256>>>(w_x2h, b_x2h, w_h2h, b_h2h);
    rec_kernel<<<RCTA, 256, REC_SMEM>>>(x);
    fc_kernel<<<BB, 256>>>(w_fc, b_fc, out);
}